// round 15
// baseline (speedup 1.0000x reference)
#include <cuda_runtime.h>
#include <cuda_bf16.h>
#include <cstdint>

// GCN on complete graph + self-loops == per-batch mean pooling -> per-batch
// 4-layer MLP on the mean node feature.
// Single-kernel tensor-core version: warp-level mma.sync.m16n8k16 (bf16,
// f32 accum, hi/lo split = 3 MMAs/step). Each CTA converts W2/Wm1 to
// transposed bf16 hi/lo smem tiles in-kernel (coalesced LDG, conflict-free
// STS). L1 (K=14) is scalar f32. grid=64 CTAs x 16 batch rows, NT=512.
// R15 fix: sWm2v staging covered only 384/512 entries -> tail read garbage.

#define NT 512
#define MR 16
#define KPAD 136    // u16 k-stride (u32 stride 68) -> conflict-free frag LDS

// ---- dynamic smem byte offsets ----
#define OW2H 0
#define WB   (128 * KPAD * 2)      // 34816
#define OW2L (OW2H + WB)
#define OM1H (OW2L + WB)
#define OM1L (OM1H + WB)
#define OA1H (OM1L + WB)           // 139264, act tiles 16 x KPAD u16
#define AB   (MR * KPAD * 2)       // 4352
#define OA1L (OA1H + AB)
#define OA2H (OA1L + AB)
#define OA2L (OA2H + AB)
#define OSM  (OA2L + AB)           // 156672, f32 [16][132]
#define OFB  (OSM + 16 * 132 * 4)  // 165120, f32 [16][16]
#define OPART (OFB + 1024)         // 166144, float2 [448]
#define OB2V (OPART + 3584)        // 169728
#define OBM1 (OB2V + 512)          // 170240
#define OWM2 (OBM1 + 512)          // 170752, f32 [512]
#define OBM2 (OWM2 + 2048)         // 172800, f32 [4]
#define OSP  (OBM2 + 16)           // 172816, f32 [512]
#define OSO  (OSP + 2048)          // 174864, f32 [64]
#define SMEM_BYTES (OSO + 256)     // 175120

__device__ __forceinline__ uint32_t packbf(float lo, float hi) {
    uint32_t r;
    asm("cvt.rn.bf16x2.f32 %0, %1, %2;" : "=r"(r) : "f"(hi), "f"(lo));
    return r;
}
__device__ __forceinline__ void split2u(float x0, float x1, uint32_t& hp, uint32_t& lp) {
    hp = packbf(x0, x1);
    const float h0 = __uint_as_float(hp << 16);
    const float h1 = __uint_as_float(hp & 0xFFFF0000u);
    lp = packbf(x0 - h0, x1 - h1);
}

__device__ __forceinline__ void mma16816(float c[4],
                                         uint32_t a0, uint32_t a1, uint32_t a2, uint32_t a3,
                                         uint32_t b0, uint32_t b1) {
    asm volatile(
        "mma.sync.aligned.m16n8k16.row.col.f32.bf16.bf16.f32 "
        "{%0,%1,%2,%3}, {%4,%5,%6,%7}, {%8,%9}, {%0,%1,%2,%3};"
        : "+f"(c[0]), "+f"(c[1]), "+f"(c[2]), "+f"(c[3])
        : "r"(a0), "r"(a1), "r"(a2), "r"(a3), "r"(b0), "r"(b1));
}

// One 128-k layer: act hi/lo [16][KPAD] u16 smem, weights hi/lo [128][KPAD]
// u16 smem (transposed: Wt[n][k]). 16 warps x 8-col n-tile, M=16.
// Output: bf16 hi/lo act tiles, or f32 sM[16][132].
template<bool F32OUT>
__device__ __forceinline__ void layer128(
    const unsigned short* __restrict__ sInHi, const unsigned short* __restrict__ sInLo,
    const unsigned short* __restrict__ sWhi,  const unsigned short* __restrict__ sWlo,
    const float* __restrict__ bias,
    unsigned short* __restrict__ sOutHi, unsigned short* __restrict__ sOutLo,
    float* __restrict__ sMout, int wid, int lane)
{
    const int g = lane >> 2, t = lane & 3;
    const int n0 = wid * 8 + g;
    float c0[4] = {0.f, 0.f, 0.f, 0.f};

    #pragma unroll
    for (int s = 0; s < 8; s++) {
        const int ko = 16 * s + 2 * t;
        const uint32_t ah0 = *(const uint32_t*)(sInHi + g * KPAD + ko);
        const uint32_t ah1 = *(const uint32_t*)(sInHi + (g + 8) * KPAD + ko);
        const uint32_t ah2 = *(const uint32_t*)(sInHi + g * KPAD + ko + 8);
        const uint32_t ah3 = *(const uint32_t*)(sInHi + (g + 8) * KPAD + ko + 8);
        const uint32_t al0 = *(const uint32_t*)(sInLo + g * KPAD + ko);
        const uint32_t al1 = *(const uint32_t*)(sInLo + (g + 8) * KPAD + ko);
        const uint32_t al2 = *(const uint32_t*)(sInLo + g * KPAD + ko + 8);
        const uint32_t al3 = *(const uint32_t*)(sInLo + (g + 8) * KPAD + ko + 8);

        const uint32_t bh0 = *(const uint32_t*)(sWhi + n0 * KPAD + ko);
        const uint32_t bh1 = *(const uint32_t*)(sWhi + n0 * KPAD + ko + 8);
        const uint32_t bl0 = *(const uint32_t*)(sWlo + n0 * KPAD + ko);
        const uint32_t bl1 = *(const uint32_t*)(sWlo + n0 * KPAD + ko + 8);

        mma16816(c0, ah0, ah1, ah2, ah3, bh0, bh1);   // hi*hi
        mma16816(c0, ah0, ah1, ah2, ah3, bl0, bl1);   // hi*lo
        mma16816(c0, al0, al1, al2, al3, bh0, bh1);   // lo*hi
    }

    const int col = wid * 8 + 2 * t;
    const float bx = bias[col], by = bias[col + 1];
    const float x0 = fmaxf(c0[0] + bx, 0.f);
    const float x1 = fmaxf(c0[1] + by, 0.f);
    const float x2 = fmaxf(c0[2] + bx, 0.f);
    const float x3 = fmaxf(c0[3] + by, 0.f);
    if (F32OUT) {
        *(float2*)(sMout + g * 132 + col)       = make_float2(x0, x1);
        *(float2*)(sMout + (g + 8) * 132 + col) = make_float2(x2, x3);
    } else {
        uint32_t hp, lp;
        split2u(x0, x1, hp, lp);
        *(uint32_t*)(sOutHi + g * KPAD + col) = hp;
        *(uint32_t*)(sOutLo + g * KPAD + col) = lp;
        split2u(x2, x3, hp, lp);
        *(uint32_t*)(sOutHi + (g + 8) * KPAD + col) = hp;
        *(uint32_t*)(sOutLo + (g + 8) * KPAD + col) = lp;
    }
}

// Convert one f32 weight matrix W[k][n] (128x128) into transposed bf16 hi/lo
// tiles Wt[n][k] in smem. Warp-tiled: tile = it*16 + wid covers (nb,kb);
// lane: dn = lane&7, dk = lane>>3. Coalesced LDG; conflict-free STS.
__device__ __forceinline__ void convert_w(const float* __restrict__ W,
                                          unsigned short* __restrict__ sH,
                                          unsigned short* __restrict__ sL,
                                          int wid, int lane)
{
    const int dn = lane & 7, dk = lane >> 3;
    #pragma unroll
    for (int it = 0; it < 16; it++) {
        const int tile = it * 16 + wid;
        const int nb = tile & 15, kb = tile >> 4;
        const int n = nb * 8 + dn;
        const int k = kb * 8 + dk * 2;
        const float v0 = W[k * 128 + n];
        const float v1 = W[(k + 1) * 128 + n];
        uint32_t hp, lp;
        split2u(v0, v1, hp, lp);
        ((uint32_t*)sH)[n * (KPAD / 2) + (k >> 1)] = hp;
        ((uint32_t*)sL)[n * (KPAD / 2) + (k >> 1)] = lp;
    }
}

__global__ __launch_bounds__(NT, 1) void gcnn_tc_kernel(
    const float* __restrict__ obs,
    const float* __restrict__ W1,  const float* __restrict__ b1,
    const float* __restrict__ W2,  const float* __restrict__ b2,
    const float* __restrict__ Wm1, const float* __restrict__ bm1,
    const float* __restrict__ Wm2, const float* __restrict__ bm2,
    float* __restrict__ out, int std_off)
{
    extern __shared__ __align__(16) char smem[];
    unsigned short* sW2h = (unsigned short*)(smem + OW2H);
    unsigned short* sW2l = (unsigned short*)(smem + OW2L);
    unsigned short* sM1h = (unsigned short*)(smem + OM1H);
    unsigned short* sM1l = (unsigned short*)(smem + OM1L);
    unsigned short* sA1h = (unsigned short*)(smem + OA1H);
    unsigned short* sA1l = (unsigned short*)(smem + OA1L);
    unsigned short* sA2h = (unsigned short*)(smem + OA2H);
    unsigned short* sA2l = (unsigned short*)(smem + OA2L);
    float*  sM    = (float*)(smem + OSM);
    float*  sFB   = (float*)(smem + OFB);
    float2* sPart = (float2*)(smem + OPART);
    float*  sB2   = (float*)(smem + OB2V);
    float*  sBm1  = (float*)(smem + OBM1);
    float*  sWm2v = (float*)(smem + OWM2);
    float*  sBm2  = (float*)(smem + OBM2);
    float*  sP    = (float*)(smem + OSP);
    float*  sO    = (float*)(smem + OSO);

    const int tid = threadIdx.x, wid = tid >> 5, lane = tid & 31;
    const int base = blockIdx.x * MR;

    // ---- in-kernel weight conversion (no prep kernel, no TMA) ----
    convert_w(W2,  sW2h, sW2l, wid, lane);
    convert_w(Wm1, sM1h, sM1l, wid, lane);

    // ---- small params (FIX: all 512 Wm2 entries staged) ----
    sWm2v[tid] = Wm2[tid];
    if (tid < 128) { sB2[tid] = b2[tid]; sBm1[tid] = bm1[tid]; }
    if (tid < 4) sBm2[tid] = bm2[tid];

    // ---- fbar partials: 448 threads = 16r x 7 dim-pairs x 4 node-quarters ----
    if (tid < 448) {
        const int r = tid & 15, pq = tid >> 4;      // pq 0..27
        const int p = pq % 7, q = pq / 7;
        const float* s = obs + (size_t)(base + r) * 512 + 2 + 2 * p + q * 128;
        float s0 = 0.f, s1 = 0.f;
        #pragma unroll
        for (int n = 0; n < 8; n++) {
            const float2 v = *(const float2*)(s + n * 16);
            s0 += v.x; s1 += v.y;
        }
        sPart[r * 28 + pq] = make_float2(s0, s1);
    }
    __syncthreads();

    // ---- fbar reduce: 112 threads (r, p) ----
    if (tid < 112) {
        const int r = tid & 15, p = tid >> 4;       // p 0..6
        float s0 = 0.f, s1 = 0.f;
        #pragma unroll
        for (int q = 0; q < 4; q++) {
            const float2 v = sPart[r * 28 + q * 7 + p];
            s0 += v.x; s1 += v.y;
        }
        sFB[r * 16 + 2 * p]     = s0 * 0.03125f;
        sFB[r * 16 + 2 * p + 1] = s1 * 0.03125f;
    }
    __syncthreads();

    // ---- L1 scalar: h1 = relu(fbar @ W1 + b1) -> A2 bf16 hi/lo tiles ----
    {
        const int r = tid >> 5, j = tid & 31, c0 = 4 * j;
        float4 acc = *(const float4*)(b1 + c0);
        #pragma unroll
        for (int d = 0; d < 14; d++) {
            const float f = sFB[r * 16 + d];
            const float4 w = *(const float4*)(W1 + d * 128 + c0);
            acc.x = fmaf(f, w.x, acc.x);
            acc.y = fmaf(f, w.y, acc.y);
            acc.z = fmaf(f, w.z, acc.z);
            acc.w = fmaf(f, w.w, acc.w);
        }
        acc.x = fmaxf(acc.x, 0.f); acc.y = fmaxf(acc.y, 0.f);
        acc.z = fmaxf(acc.z, 0.f); acc.w = fmaxf(acc.w, 0.f);
        uint32_t hp, lp;
        split2u(acc.x, acc.y, hp, lp);
        ((uint32_t*)sA2h)[r * (KPAD / 2) + 2 * j]     = hp;
        ((uint32_t*)sA2l)[r * (KPAD / 2) + 2 * j]     = lp;
        split2u(acc.z, acc.w, hp, lp);
        ((uint32_t*)sA2h)[r * (KPAD / 2) + 2 * j + 1] = hp;
        ((uint32_t*)sA2l)[r * (KPAD / 2) + 2 * j + 1] = lp;
    }
    __syncthreads();

    // ---- L2: h2 = relu(h1 @ W2 + b2) : A2 -> A1 ----
    layer128<false>(sA2h, sA2l, sW2h, sW2l, sB2, sA1h, sA1l, nullptr, wid, lane);
    __syncthreads();

    // ---- L3: m = relu(h2 @ Wm1 + bm1) : A1 -> sM f32 ----
    layer128<true>(sA1h, sA1l, sM1h, sM1l, sBm1, nullptr, nullptr, sM, wid, lane);
    __syncthreads();

    // ---- tail: o = m @ Wm2 + bm2 : 512 = 16r x 4c x 8 k-slices ----
    {
        const int r = tid >> 5, cc = (tid >> 3) & 3, s = tid & 7;
        float p = 0.f;
        #pragma unroll
        for (int i = 0; i < 16; i++) {
            const int k = s * 16 + i;
            p = fmaf(sM[r * 132 + k], sWm2v[k * 4 + cc], p);
        }
        sP[tid] = p;
    }
    __syncthreads();
    if (tid < 64) {
        const int r = tid >> 2, cc = tid & 3;
        float o = sBm2[cc];
        #pragma unroll
        for (int s = 0; s < 8; s++) o += sP[r * 32 + cc * 8 + s];
        if (cc >= 2) o = __expf(-5.0f + 3.5f * (tanhf(o) + 1.0f));
        sO[r * 4 + cc] = o;    // [mu0, mu1, std0, std1]
    }
    __syncthreads();

    // ---- write: 512 float4 stores, one per thread, coalesced ----
    {
        const int plane = tid >> 8;           // 0 = mu, 1 = std
        const int r = (tid >> 4) & 15;
        const int q = tid & 15;
        const float v0 = sO[r * 4 + 2 * plane];
        const float v1 = sO[r * 4 + 2 * plane + 1];
        float* dst = out + (plane ? (size_t)std_off : 0) + (size_t)(base + r) * 64;
        ((float4*)dst)[q] = make_float4(v0, v1, v0, v1);
    }
}

extern "C" void kernel_launch(void* const* d_in, const int* in_sizes, int n_in,
                              void* d_out, int out_size) {
    const float* obs = (const float*)d_in[0];
    const float* W1  = (const float*)d_in[1];
    const float* b1  = (const float*)d_in[2];
    const float* W2  = (const float*)d_in[3];
    const float* b2  = (const float*)d_in[4];
    const float* Wm1 = (const float*)d_in[5];
    const float* bm1 = (const float*)d_in[6];
    const float* Wm2 = (const float*)d_in[7];
    const float* bm2 = (const float*)d_in[8];
    float* out = (float*)d_out;

    const int bs = in_sizes[0] / 512;     // 1024
    const int std_off = bs * 64;
    const int grid = bs / MR;             // 64

    cudaFuncSetAttribute(gcnn_tc_kernel,
                         cudaFuncAttributeMaxDynamicSharedMemorySize, SMEM_BYTES);
    gcnn_tc_kernel<<<grid, NT, SMEM_BYTES>>>(obs, W1, b1, W2, b2, Wm1, bm1,
                                             Wm2, bm2, out, std_off);
}